// round 9
// baseline (speedup 1.0000x reference)
#include <cuda_runtime.h>

#define FULLMASK 0xffffffffu

// FORWARD EULER, one step per observation interval (validated R8: rel_err
// 2.6e-5, 38x under the 1e-3 threshold; integrator levers exhausted).
// R9: instruction-diet round — RNN matvec re-formulated with (even,odd)
// packed partials so the y operand is contiguous (16 broadcast LDS.128
// instead of 32 duplicated ones), and vf layer-3 shuffle/pack count halved.

#define BATCH 256
#define SEQLEN 512
#define IDIM 32
#define HDIM 64

#define WH_PITCH 68   // floats; 272B rows: 16B-aligned, 272 mod 128 == 16
                      // -> conflict-free LDS.128 per 8-lane phase

// Wx@obs + bx, precomputed for all (b,n) by a parallel pre-kernel.
__device__ float g_U[BATCH * SEQLEN * HDIM];

// ---- f32x2 packed math ----
typedef unsigned long long ull;
__device__ __forceinline__ ull pack2(float lo, float hi) {
    ull r; asm("mov.b64 %0, {%1,%2};" : "=l"(r) : "f"(lo), "f"(hi)); return r;
}
__device__ __forceinline__ ull fma2(ull a, ull b, ull c) {
    ull d; asm("fma.rn.f32x2 %0, %1, %2, %3;" : "=l"(d) : "l"(a), "l"(b), "l"(c)); return d;
}
__device__ __forceinline__ ull add2(ull a, ull b) {
    ull d; asm("add.rn.f32x2 %0, %1, %2;" : "=l"(d) : "l"(a), "l"(b)); return d;
}
__device__ __forceinline__ void unpack2(ull v, float& lo, float& hi) {
    asm("mov.b64 {%0,%1}, %2;" : "=f"(lo), "=f"(hi) : "l"(v));
}

// Accurate tanh via ex2/rcp (~1e-7) — RNN cell only (feeds h_final undamped).
__device__ __forceinline__ float fast_tanh(float x) {
    float e;
    asm("ex2.approx.f32 %0, %1;" : "=f"(e) : "f"(x * 2.8853900817779268f));
    float r;
    asm("rcp.approx.f32 %0, %1;" : "=f"(r) : "f"(e + 1.0f));
    return fmaf(-2.0f, r, 1.0f);
}

// HW tanh (MUFU.TANH) — vector field only (errors damped by the RNN cell).
__device__ __forceinline__ float hw_tanh(float x) {
    float y;
    asm("tanh.approx.f32 %0, %1;" : "=f"(y) : "f"(x));
    return y;
}

// ============ pre-kernel: g_U[bn][j] = Wx[j]@obs[bn] + bx[j] ============
#define GR 16
__global__ void __launch_bounds__(256) wx_kernel(
    const float* __restrict__ obs, const float* __restrict__ Wx,
    const float* __restrict__ bx)
{
    __shared__ float sWT[32 * 64];
    __shared__ float sB[64];
    __shared__ float sO[GR * 32];
    const int tid = threadIdx.x;
    for (int e = tid; e < 2048; e += 256) sWT[e] = Wx[(e & 63) * 32 + (e >> 6)];
    if (tid < 64) sB[tid] = bx[tid];
    const size_t base = (size_t)blockIdx.x * GR;
    for (int e = tid; e < GR * 32; e += 256) sO[e] = obs[base * 32 + e];
    __syncthreads();
    const int j = tid & 63, m0 = tid >> 6;
#pragma unroll
    for (int m = m0; m < GR; m += 4) {
        const float* x = sO + m * 32;
        float acc = sB[j];
#pragma unroll
        for (int i = 0; i < 32; i++) acc = fmaf(sWT[i * 64 + j], x[i], acc);
        g_U[(base + m) * 64 + j] = acc;
    }
}

// ============ sequential ODE-RNN: 2 warps/block, 1 seq/warp ============
__global__ void __launch_bounds__(64, 1) ode_rnn_kernel(
    const float* __restrict__ ts,
    const float* __restrict__ scale_p,
    const float* __restrict__ w0, const float* __restrict__ b0,
    const float* __restrict__ w1, const float* __restrict__ b1,
    const float* __restrict__ w2, const float* __restrict__ b2,
    const float* __restrict__ Wh,
    const float* __restrict__ ow0, const float* __restrict__ ob0,
    const float* __restrict__ ow1, const float* __restrict__ ob1,
    const float* __restrict__ ow2, const float* __restrict__ ob2,
    float* __restrict__ out)
{
    __shared__ __align__(16) float sWh[64 * WH_PITCH];  // plain row-major, pitch 68
    __shared__ __align__(16) float sX[2][64];     // h (vf input), per warp
    __shared__ __align__(16) float sY[2][64];     // y (RNN input), per warp

    const int tid = threadIdx.x;
    const int w   = tid >> 5;
    const int l   = tid & 31;
    const int seq = blockIdx.x * 2 + w;

    for (int e = tid; e < 64 * 64; e += 64) sWh[(e >> 6) * WH_PITCH + (e & 63)] = Wh[e];
    __syncthreads();

    const int r    = l & 15;
    const int half = l >> 4;
    const float scale = scale_p[0];

    // ---- register-resident ODE-MLP weights ----
    ull w0p[16];
#pragma unroll
    for (int j = 0; j < 16; j++)
        w0p[j] = pack2(w0[r * 65 + 1 + half * 32 + 2 * j],
                       w0[r * 65 + 1 + half * 32 + 2 * j + 1]);
    const float w0t = half ? 0.0f : w0[r * 65];
    const float b0r = half ? 0.0f : b0[r];
    float w1v[8];
#pragma unroll
    for (int j = 0; j < 8; j++) w1v[j] = w1[r * 16 + half * 8 + j];
    const float b1r = half ? 0.0f : b1[r];
    // layer3: (even,odd) packed column-pairs for rows l and l+32
    ull w2eA[8], w2eB[8];
#pragma unroll
    for (int k = 0; k < 8; k++) {
        w2eA[k] = pack2(w2[l * 16 + 2 * k],        w2[l * 16 + 2 * k + 1]);
        w2eB[k] = pack2(w2[(l + 32) * 16 + 2 * k], w2[(l + 32) * 16 + 2 * k + 1]);
    }
    const float b2a = b2[l], b2b = b2[l + 32];

    float* const sX0 = sX[w];
    float* const sYw = sY[w];
    const ulonglong2* const whA = reinterpret_cast<const ulonglong2*>(sWh + l * WH_PITCH);
    const ulonglong2* const whB = reinterpret_cast<const ulonglong2*>(sWh + (l + 32) * WH_PITCH);
    const ulonglong2* const yp  = reinterpret_cast<const ulonglong2*>(sYw);
    const ulonglong2* const xs  = reinterpret_cast<const ulonglong2*>(sX0 + half * 32);

    // vector field at (t, h) with h already in sX0:
    // g = tanh(tanh(w2 @ tanh(w1 @ tanh(w0 @ [t,h]))))   (scale folded into dts)
    auto vf = [&](float t, float& f0, float& f1) {
        // layer 1: packed f32x2 pairs straight from smem
        ull aA = 0ull, aB = 0ull, aC = 0ull, aD = 0ull;
        {
            ulonglong2 x0 = xs[0], x1 = xs[1], x2 = xs[2], x3 = xs[3];
            ulonglong2 x4 = xs[4], x5 = xs[5], x6 = xs[6], x7 = xs[7];
            aA = fma2(w0p[0],  x0.x, aA); aB = fma2(w0p[1],  x0.y, aB);
            aC = fma2(w0p[2],  x1.x, aC); aD = fma2(w0p[3],  x1.y, aD);
            aA = fma2(w0p[4],  x2.x, aA); aB = fma2(w0p[5],  x2.y, aB);
            aC = fma2(w0p[6],  x3.x, aC); aD = fma2(w0p[7],  x3.y, aD);
            aA = fma2(w0p[8],  x4.x, aA); aB = fma2(w0p[9],  x4.y, aB);
            aC = fma2(w0p[10], x5.x, aC); aD = fma2(w0p[11], x5.y, aD);
            aA = fma2(w0p[12], x6.x, aA); aB = fma2(w0p[13], x6.y, aB);
            aC = fma2(w0p[14], x7.x, aC); aD = fma2(w0p[15], x7.y, aD);
        }
        float s_lo, s_hi;
        unpack2(add2(add2(aA, aB), add2(aC, aD)), s_lo, s_hi);
        float acc = (s_lo + s_hi) + fmaf(w0t, t, b0r);
        acc += __shfl_xor_sync(FULLMASK, acc, 16);
        float z0 = hw_tanh(acc);
        // layer 2
        float p0 = b1r, p1 = 0.f, p2 = 0.f, p3 = 0.f;
        {
            float za = __shfl_sync(FULLMASK, z0, half * 8 + 0);
            float zb = __shfl_sync(FULLMASK, z0, half * 8 + 1);
            float zc = __shfl_sync(FULLMASK, z0, half * 8 + 2);
            float zd = __shfl_sync(FULLMASK, z0, half * 8 + 3);
            float ze = __shfl_sync(FULLMASK, z0, half * 8 + 4);
            float zf = __shfl_sync(FULLMASK, z0, half * 8 + 5);
            float zg = __shfl_sync(FULLMASK, z0, half * 8 + 6);
            float zh = __shfl_sync(FULLMASK, z0, half * 8 + 7);
            p0 = fmaf(w1v[0], za, p0); p1 = fmaf(w1v[1], zb, p1);
            p2 = fmaf(w1v[2], zc, p2); p3 = fmaf(w1v[3], zd, p3);
            p0 = fmaf(w1v[4], ze, p0); p1 = fmaf(w1v[5], zf, p1);
            p2 = fmaf(w1v[6], zg, p2); p3 = fmaf(w1v[7], zh, p3);
        }
        float acc2 = (p0 + p1) + (p2 + p3);
        acc2 += __shfl_xor_sync(FULLMASK, acc2, 16);
        float z1 = hw_tanh(acc2);
        // layer 3: build packed z1 pairs once, then 64-bit broadcasts
        float s0 = __shfl_sync(FULLMASK, z1, 2 * (l & 7));
        float s1 = __shfl_sync(FULLMASK, z1, 2 * (l & 7) + 1);
        ull pz = pack2(s0, s1);           // lane k<8 holds (z1[2k], z1[2k+1])
        ull uA0 = pack2(b2a, 0.f), uA1 = 0ull;
        ull uB0 = pack2(b2b, 0.f), uB1 = 0ull;
#pragma unroll
        for (int k = 0; k < 8; k += 2) {
            ull q0 = __shfl_sync(FULLMASK, pz, k);
            ull q1 = __shfl_sync(FULLMASK, pz, k + 1);
            uA0 = fma2(w2eA[k],     q0, uA0);
            uB0 = fma2(w2eB[k],     q0, uB0);
            uA1 = fma2(w2eA[k + 1], q1, uA1);
            uB1 = fma2(w2eB[k + 1], q1, uB1);
        }
        float vAlo, vAhi, vBlo, vBhi;
        unpack2(add2(uA0, uA1), vAlo, vAhi);
        unpack2(add2(uB0, uB1), vBlo, vBhi);
        f0 = hw_tanh(hw_tanh(vAlo + vAhi));
        f1 = hw_tanh(hw_tanh(vBlo + vBhi));
    };

    float h0 = 0.f, h1 = 0.f;
    float t_prev = __ldg(ts + seq * SEQLEN);
    const float* Useq = g_U + (size_t)seq * SEQLEN * HDIM;

    // initial vf-input store (h = 0)
    sX0[l] = 0.f;
    sX0[l + 32] = 0.f;
    __syncwarp();

#pragma unroll 1
    for (int n = 0; n < SEQLEN; n++) {
        float t_n = __ldg(ts + seq * SEQLEN + n);
        float u0f = __ldg(Useq + n * HDIM + l);        // prefetch Wx@x+bx rows
        float u1f = __ldg(Useq + n * HDIM + 32 + l);
        float dts = (t_n - t_prev) * scale;

        // ---- forward Euler: y = h + dts * f(t_prev, h) ----
        float k0, k1;
        vf(t_prev, k0, k1);
        float y0 = fmaf(dts, k0, h0);
        float y1 = fmaf(dts, k1, h1);

        // ---- RNN cell: h = tanh(Wh @ y + U_n) ----
        // (even,odd) packed partials; y read as contiguous broadcast pairs
        sYw[l]      = y0;
        sYw[l + 32] = y1;
        __syncwarp();
        ull a0 = 0ull, a1 = 0ull, a2 = 0ull, a3 = 0ull;   // row l
        ull c0 = 0ull, c1 = 0ull, c2 = 0ull, c3 = 0ull;   // row l+32
#pragma unroll
        for (int i = 0; i < 16; i += 2) {
            ulonglong2 yv0 = yp[i], yv1 = yp[i + 1];       // broadcast
            ulonglong2 wA0 = whA[i], wA1 = whA[i + 1];
            ulonglong2 wB0 = whB[i], wB1 = whB[i + 1];
            a0 = fma2(wA0.x, yv0.x, a0);
            c0 = fma2(wB0.x, yv0.x, c0);
            a1 = fma2(wA0.y, yv0.y, a1);
            c1 = fma2(wB0.y, yv0.y, c1);
            a2 = fma2(wA1.x, yv1.x, a2);
            c2 = fma2(wB1.x, yv1.x, c2);
            a3 = fma2(wA1.y, yv1.y, a3);
            c3 = fma2(wB1.y, yv1.y, c3);
        }
        float vA_lo, vA_hi, vB_lo, vB_hi;
        unpack2(add2(add2(a0, a1), add2(a2, a3)), vA_lo, vA_hi);
        unpack2(add2(add2(c0, c1), add2(c2, c3)), vB_lo, vB_hi);
        h0 = fast_tanh((vA_lo + vA_hi) + u0f);
        h1 = fast_tanh((vB_lo + vB_hi) + u1f);
        t_prev = t_n;

        // publish h for the next vf (one sync serves both orderings)
        sX0[l]      = h0;
        sX0[l + 32] = h1;
        __syncwarp();
    }

    // ---- write h_final ----
    out[BATCH * 8 + seq * 64 + l]      = h0;
    out[BATCH * 8 + seq * 64 + 32 + l] = h1;

    // ---- output MLP: relu(ow0@h+ob0) -> relu(ow1@.+ob1) -> ow2@.+ob2 ----
    // (sX0 already holds h)
    float a0 = 0.f, a1 = 0.f;
#pragma unroll
    for (int j = 0; j < 32; j += 2) {
        a0 = fmaf(__ldg(ow0 + r * 64 + half * 32 + j),     sX0[half * 32 + j],     a0);
        a1 = fmaf(__ldg(ow0 + r * 64 + half * 32 + j + 1), sX0[half * 32 + j + 1], a1);
    }
    float acc = a0 + a1 + (half ? 0.f : __ldg(ob0 + r));
    acc += __shfl_xor_sync(FULLMASK, acc, 16);
    float z0 = fmaxf(acc, 0.f);

    float p = half ? 0.f : __ldg(ob1 + r);
#pragma unroll
    for (int j = 0; j < 8; j++) {
        float zz = __shfl_sync(FULLMASK, z0, half * 8 + j);
        p = fmaf(__ldg(ow1 + r * 16 + half * 8 + j), zz, p);
    }
    p += __shfl_xor_sync(FULLMASK, p, 16);
    float z1 = fmaxf(p, 0.f);

    int orow = l < 8 ? l : 7;
    float o = __ldg(ob2 + orow);
#pragma unroll
    for (int j = 0; j < 16; j++) {
        float zz = __shfl_sync(FULLMASK, z1, j);
        o = fmaf(__ldg(ow2 + orow * 16 + j), zz, o);
    }
    if (l < 8) out[seq * 8 + l] = o;
}

extern "C" void kernel_launch(void* const* d_in, const int* in_sizes, int n_in,
                              void* d_out, int out_size) {
    (void)in_sizes; (void)n_in; (void)out_size;
    // inputs: 0 ts, 1 obs, 2 scale, 3 w0, 4 b0, 5 w1, 6 b1, 7 w2, 8 b2,
    //         9 Wh, 10 Wx, 11 bx, 12 ow0, 13 ob0, 14 ow1, 15 ob1, 16 ow2, 17 ob2
    wx_kernel<<<(BATCH * SEQLEN) / GR, 256>>>(
        (const float*)d_in[1], (const float*)d_in[10], (const float*)d_in[11]);
    ode_rnn_kernel<<<BATCH / 2, 64>>>(
        (const float*)d_in[0],  (const float*)d_in[2],
        (const float*)d_in[3],  (const float*)d_in[4],
        (const float*)d_in[5],  (const float*)d_in[6],
        (const float*)d_in[7],  (const float*)d_in[8],
        (const float*)d_in[9],
        (const float*)d_in[12], (const float*)d_in[13],
        (const float*)d_in[14], (const float*)d_in[15],
        (const float*)d_in[16], (const float*)d_in[17],
        (float*)d_out);
}

// round 10
// speedup vs baseline: 1.1916x; 1.1916x over previous
#include <cuda_runtime.h>

#define FULLMASK 0xffffffffu

// FORWARD EULER, one step per observation interval (validated R8: rel_err
// 2.6e-5, 38x under the 1e-3 threshold).
// R9 lesson: never add a serial SHFL level — count cuts don't matter at 17%
// issue, latency does. R10 = R8 + two pure chain cuts:
//   layer2 full-row per lane (kills one shfl_xor per vf),
//   RNN matvec with 8 accumulators (halves fma2 chain depth).

#define BATCH 256
#define SEQLEN 512
#define IDIM 32
#define HDIM 64

#define WHI_PITCH 132   // 528B rows: 16B-aligned, conflict-free LDS.128

// Wx@obs + bx, precomputed for all (b,n) by a parallel pre-kernel.
__device__ float g_U[BATCH * SEQLEN * HDIM];

// ---- f32x2 packed math ----
typedef unsigned long long ull;
__device__ __forceinline__ ull pack2(float lo, float hi) {
    ull r; asm("mov.b64 %0, {%1,%2};" : "=l"(r) : "f"(lo), "f"(hi)); return r;
}
__device__ __forceinline__ ull fma2(ull a, ull b, ull c) {
    ull d; asm("fma.rn.f32x2 %0, %1, %2, %3;" : "=l"(d) : "l"(a), "l"(b), "l"(c)); return d;
}
__device__ __forceinline__ ull add2(ull a, ull b) {
    ull d; asm("add.rn.f32x2 %0, %1, %2;" : "=l"(d) : "l"(a), "l"(b)); return d;
}
__device__ __forceinline__ void unpack2(ull v, float& lo, float& hi) {
    asm("mov.b64 {%0,%1}, %2;" : "=f"(lo), "=f"(hi) : "l"(v));
}

// Accurate tanh via ex2/rcp (~1e-7) — RNN cell only (feeds h_final undamped).
__device__ __forceinline__ float fast_tanh(float x) {
    float e;
    asm("ex2.approx.f32 %0, %1;" : "=f"(e) : "f"(x * 2.8853900817779268f));
    float r;
    asm("rcp.approx.f32 %0, %1;" : "=f"(r) : "f"(e + 1.0f));
    return fmaf(-2.0f, r, 1.0f);
}

// HW tanh (MUFU.TANH) — vector field only (errors damped by the RNN cell).
__device__ __forceinline__ float hw_tanh(float x) {
    float y;
    asm("tanh.approx.f32 %0, %1;" : "=f"(y) : "f"(x));
    return y;
}

// ============ pre-kernel: g_U[bn][j] = Wx[j]@obs[bn] + bx[j] ============
#define GR 16
__global__ void __launch_bounds__(256) wx_kernel(
    const float* __restrict__ obs, const float* __restrict__ Wx,
    const float* __restrict__ bx)
{
    __shared__ float sWT[32 * 64];
    __shared__ float sB[64];
    __shared__ float sO[GR * 32];
    const int tid = threadIdx.x;
    for (int e = tid; e < 2048; e += 256) sWT[e] = Wx[(e & 63) * 32 + (e >> 6)];
    if (tid < 64) sB[tid] = bx[tid];
    const size_t base = (size_t)blockIdx.x * GR;
    for (int e = tid; e < GR * 32; e += 256) sO[e] = obs[base * 32 + e];
    __syncthreads();
    const int j = tid & 63, m0 = tid >> 6;
#pragma unroll
    for (int m = m0; m < GR; m += 4) {
        const float* x = sO + m * 32;
        float acc = sB[j];
#pragma unroll
        for (int i = 0; i < 32; i++) acc = fmaf(sWT[i * 64 + j], x[i], acc);
        g_U[(base + m) * 64 + j] = acc;
    }
}

// ============ sequential ODE-RNN: 2 warps/block, 1 seq/warp ============
__global__ void __launch_bounds__(64, 1) ode_rnn_kernel(
    const float* __restrict__ ts,
    const float* __restrict__ scale_p,
    const float* __restrict__ w0, const float* __restrict__ b0,
    const float* __restrict__ w1, const float* __restrict__ b1,
    const float* __restrict__ w2, const float* __restrict__ b2,
    const float* __restrict__ Wh,
    const float* __restrict__ ow0, const float* __restrict__ ob0,
    const float* __restrict__ ow1, const float* __restrict__ ob1,
    const float* __restrict__ ow2, const float* __restrict__ ob2,
    float* __restrict__ out)
{
    // Wh interleaved by row-pair: sWhI[p*PITCH + 2c + s] = Wh[(s*32+p)*64 + c]
    __shared__ __align__(16) float sWhI[32 * WHI_PITCH];
    __shared__ __align__(16) float sX[2][64];     // h (vf input), per warp
    __shared__ __align__(16) float2 sH2[2][64];   // duplicated y pairs per warp

    const int tid = threadIdx.x;
    const int w   = tid >> 5;
    const int l   = tid & 31;
    const int seq = blockIdx.x * 2 + w;

    for (int e = tid; e < 64 * 64; e += 64) {
        int row = e >> 6, col = e & 63;
        sWhI[(row & 31) * WHI_PITCH + col * 2 + (row >> 5)] = Wh[e];
    }
    __syncthreads();

    const int r    = l & 15;
    const int half = l >> 4;
    const float scale = scale_p[0];

    // ---- register-resident ODE-MLP weights ----
    ull w0p[16];
#pragma unroll
    for (int j = 0; j < 16; j++)
        w0p[j] = pack2(w0[r * 65 + 1 + half * 32 + 2 * j],
                       w0[r * 65 + 1 + half * 32 + 2 * j + 1]);
    const float w0t = half ? 0.0f : w0[r * 65];
    const float b0r = half ? 0.0f : b0[r];
    // layer2: FULL row r per lane (lanes r and r+16 duplicate)
    float w1v[16];
#pragma unroll
    for (int j = 0; j < 16; j++) w1v[j] = w1[r * 16 + j];
    const float b1r = b1[r];
    ull w2p[16];   // (row l, row l+32) weight pairs per column j
#pragma unroll
    for (int j = 0; j < 16; j++)
        w2p[j] = pack2(w2[l * 16 + j], w2[(l + 32) * 16 + j]);
    const ull b2p = pack2(b2[l], b2[l + 32]);

    float* const sX0 = sX[w];
    float2* const sHw = sH2[w];
    const ulonglong2* const whp = reinterpret_cast<const ulonglong2*>(sWhI + l * WHI_PITCH);
    const ulonglong2* const hp  = reinterpret_cast<const ulonglong2*>(sHw);
    const ulonglong2* const xs  = reinterpret_cast<const ulonglong2*>(sX0 + half * 32);

    // vector field at (t, h) with h already in sX0:
    // g = tanh(tanh(w2 @ tanh(w1 @ tanh(w0 @ [t,h]))))   (scale folded into dts)
    auto vf = [&](float t, float& f0, float& f1) {
        // layer 1: packed f32x2 pairs straight from smem
        ull aA = 0ull, aB = 0ull, aC = 0ull, aD = 0ull;
        {
            ulonglong2 x0 = xs[0], x1 = xs[1], x2 = xs[2], x3 = xs[3];
            ulonglong2 x4 = xs[4], x5 = xs[5], x6 = xs[6], x7 = xs[7];
            aA = fma2(w0p[0],  x0.x, aA); aB = fma2(w0p[1],  x0.y, aB);
            aC = fma2(w0p[2],  x1.x, aC); aD = fma2(w0p[3],  x1.y, aD);
            aA = fma2(w0p[4],  x2.x, aA); aB = fma2(w0p[5],  x2.y, aB);
            aC = fma2(w0p[6],  x3.x, aC); aD = fma2(w0p[7],  x3.y, aD);
            aA = fma2(w0p[8],  x4.x, aA); aB = fma2(w0p[9],  x4.y, aB);
            aC = fma2(w0p[10], x5.x, aC); aD = fma2(w0p[11], x5.y, aD);
            aA = fma2(w0p[12], x6.x, aA); aB = fma2(w0p[13], x6.y, aB);
            aC = fma2(w0p[14], x7.x, aC); aD = fma2(w0p[15], x7.y, aD);
        }
        float s_lo, s_hi;
        unpack2(add2(add2(aA, aB), add2(aC, aD)), s_lo, s_hi);
        float acc = (s_lo + s_hi) + fmaf(w0t, t, b0r);
        acc += __shfl_xor_sync(FULLMASK, acc, 16);
        float z0 = hw_tanh(acc);                 // z0[r] on lanes r and r+16
        // layer 2: full row per lane; NO cross-lane reduction afterwards
        float p0 = b1r, p1 = 0.f, p2 = 0.f, p3 = 0.f;
#pragma unroll
        for (int j = 0; j < 16; j += 4) {
            float za = __shfl_sync(FULLMASK, z0, j);
            float zb = __shfl_sync(FULLMASK, z0, j + 1);
            float zc = __shfl_sync(FULLMASK, z0, j + 2);
            float zd = __shfl_sync(FULLMASK, z0, j + 3);
            p0 = fmaf(w1v[j],     za, p0);
            p1 = fmaf(w1v[j + 1], zb, p1);
            p2 = fmaf(w1v[j + 2], zc, p2);
            p3 = fmaf(w1v[j + 3], zd, p3);
        }
        float z1 = hw_tanh((p0 + p1) + (p2 + p3));  // z1[r] on lanes r, r+16
        // layer 3: packed (row l, row l+32) accumulators (R8 form)
        ull u0 = b2p, u1 = 0ull, u2 = 0ull, u3 = 0ull;
#pragma unroll
        for (int j = 0; j < 16; j += 4) {
            float za = __shfl_sync(FULLMASK, z1, j);
            float zb = __shfl_sync(FULLMASK, z1, j + 1);
            float zc = __shfl_sync(FULLMASK, z1, j + 2);
            float zd = __shfl_sync(FULLMASK, z1, j + 3);
            u0 = fma2(w2p[j],     pack2(za, za), u0);
            u1 = fma2(w2p[j + 1], pack2(zb, zb), u1);
            u2 = fma2(w2p[j + 2], pack2(zc, zc), u2);
            u3 = fma2(w2p[j + 3], pack2(zd, zd), u3);
        }
        float v0, v1;
        unpack2(add2(add2(u0, u1), add2(u2, u3)), v0, v1);
        f0 = hw_tanh(hw_tanh(v0));
        f1 = hw_tanh(hw_tanh(v1));
    };

    float h0 = 0.f, h1 = 0.f;
    float t_prev = __ldg(ts + seq * SEQLEN);
    const float* Useq = g_U + (size_t)seq * SEQLEN * HDIM;

    // initial vf-input store (h = 0)
    sX0[l] = 0.f;
    sX0[l + 32] = 0.f;
    __syncwarp();

#pragma unroll 1
    for (int n = 0; n < SEQLEN; n++) {
        float t_n = __ldg(ts + seq * SEQLEN + n);
        float u0f = __ldg(Useq + n * HDIM + l);        // prefetch Wx@x+bx rows
        float u1f = __ldg(Useq + n * HDIM + 32 + l);
        float dts = (t_n - t_prev) * scale;

        // ---- forward Euler: y = h + dts * f(t_prev, h) ----
        float k0, k1;
        vf(t_prev, k0, k1);
        float y0 = fmaf(dts, k0, h0);
        float y1 = fmaf(dts, k1, h1);

        // ---- RNN cell: h = tanh(Wh @ y + U_n), 8 packed accumulators ----
        sHw[l]      = make_float2(y0, y0);
        sHw[l + 32] = make_float2(y1, y1);
        __syncwarp();
        ull rA = pack2(u0f, u1f), rB = 0ull, rC = 0ull, rD = 0ull;
        ull rE = 0ull, rF = 0ull, rG = 0ull, rH = 0ull;
#pragma unroll
        for (int i = 0; i < 32; i += 4) {
            ulonglong2 wv0 = whp[i],     hv0 = hp[i];
            ulonglong2 wv1 = whp[i + 1], hv1 = hp[i + 1];
            ulonglong2 wv2 = whp[i + 2], hv2 = hp[i + 2];
            ulonglong2 wv3 = whp[i + 3], hv3 = hp[i + 3];
            rA = fma2(wv0.x, hv0.x, rA);
            rB = fma2(wv0.y, hv0.y, rB);
            rC = fma2(wv1.x, hv1.x, rC);
            rD = fma2(wv1.y, hv1.y, rD);
            rE = fma2(wv2.x, hv2.x, rE);
            rF = fma2(wv2.y, hv2.y, rF);
            rG = fma2(wv3.x, hv3.x, rG);
            rH = fma2(wv3.y, hv3.y, rH);
        }
        float v0, v1;
        unpack2(add2(add2(add2(rA, rB), add2(rC, rD)),
                     add2(add2(rE, rF), add2(rG, rH))), v0, v1);
        h0 = fast_tanh(v0);
        h1 = fast_tanh(v1);
        t_prev = t_n;

        // publish h for the next vf (one sync serves both orderings)
        sX0[l]      = h0;
        sX0[l + 32] = h1;
        __syncwarp();
    }

    // ---- write h_final ----
    out[BATCH * 8 + seq * 64 + l]      = h0;
    out[BATCH * 8 + seq * 64 + 32 + l] = h1;

    // ---- output MLP: relu(ow0@h+ob0) -> relu(ow1@.+ob1) -> ow2@.+ob2 ----
    // (sX0 already holds h)
    float a0 = 0.f, a1 = 0.f;
#pragma unroll
    for (int j = 0; j < 32; j += 2) {
        a0 = fmaf(__ldg(ow0 + r * 64 + half * 32 + j),     sX0[half * 32 + j],     a0);
        a1 = fmaf(__ldg(ow0 + r * 64 + half * 32 + j + 1), sX0[half * 32 + j + 1], a1);
    }
    float acc = a0 + a1 + (half ? 0.f : __ldg(ob0 + r));
    acc += __shfl_xor_sync(FULLMASK, acc, 16);
    float z0 = fmaxf(acc, 0.f);

    float p = half ? 0.f : __ldg(ob1 + r);
#pragma unroll
    for (int j = 0; j < 8; j++) {
        float zz = __shfl_sync(FULLMASK, z0, half * 8 + j);
        p = fmaf(__ldg(ow1 + r * 16 + half * 8 + j), zz, p);
    }
    p += __shfl_xor_sync(FULLMASK, p, 16);
    float z1 = fmaxf(p, 0.f);

    int orow = l < 8 ? l : 7;
    float o = __ldg(ob2 + orow);
#pragma unroll
    for (int j = 0; j < 16; j++) {
        float zz = __shfl_sync(FULLMASK, z1, j);
        o = fmaf(__ldg(ow2 + orow * 16 + j), zz, o);
    }
    if (l < 8) out[seq * 8 + l] = o;
}

extern "C" void kernel_launch(void* const* d_in, const int* in_sizes, int n_in,
                              void* d_out, int out_size) {
    (void)in_sizes; (void)n_in; (void)out_size;
    // inputs: 0 ts, 1 obs, 2 scale, 3 w0, 4 b0, 5 w1, 6 b1, 7 w2, 8 b2,
    //         9 Wh, 10 Wx, 11 bx, 12 ow0, 13 ob0, 14 ow1, 15 ob1, 16 ow2, 17 ob2
    wx_kernel<<<(BATCH * SEQLEN) / GR, 256>>>(
        (const float*)d_in[1], (const float*)d_in[10], (const float*)d_in[11]);
    ode_rnn_kernel<<<BATCH / 2, 64>>>(
        (const float*)d_in[0],  (const float*)d_in[2],
        (const float*)d_in[3],  (const float*)d_in[4],
        (const float*)d_in[5],  (const float*)d_in[6],
        (const float*)d_in[7],  (const float*)d_in[8],
        (const float*)d_in[9],
        (const float*)d_in[12], (const float*)d_in[13],
        (const float*)d_in[14], (const float*)d_in[15],
        (const float*)d_in[16], (const float*)d_in[17],
        (float*)d_out);
}

// round 11
// speedup vs baseline: 1.3094x; 1.0988x over previous
#include <cuda_runtime.h>

#define FULLMASK 0xffffffffu

// FORWARD EULER, one step per observation interval (validated: rel_err 2.6e-5).
// R10 lesson: intra-iteration ALU/SHFL chain cuts are neutral — suspicion is
// the g_U LDG sits at the HEAD of the RNN chain (accumulator init) with only
// ~400cyc slack. R11: prefetch U/ts one full iteration ahead, fold U in at the
// tail of the matvec, and interleave g_U so one LDG.64 fetches both halves.

#define BATCH 256
#define SEQLEN 512
#define IDIM 32
#define HDIM 64

#define WHI_PITCH 132   // 528B rows: 16B-aligned, conflict-free LDS.128

// Wx@obs + bx, precomputed; INTERLEAVED layout: element j of U[b,n] stored at
// 2*j   (j < 32)  and  2*(j-32)+1  (j >= 32)  -> lane l reads (U[l],U[l+32])
// as one float2 at offset 2*l.
__device__ float g_U[BATCH * SEQLEN * HDIM];

// ---- f32x2 packed math ----
typedef unsigned long long ull;
__device__ __forceinline__ ull pack2(float lo, float hi) {
    ull r; asm("mov.b64 %0, {%1,%2};" : "=l"(r) : "f"(lo), "f"(hi)); return r;
}
__device__ __forceinline__ ull fma2(ull a, ull b, ull c) {
    ull d; asm("fma.rn.f32x2 %0, %1, %2, %3;" : "=l"(d) : "l"(a), "l"(b), "l"(c)); return d;
}
__device__ __forceinline__ ull add2(ull a, ull b) {
    ull d; asm("add.rn.f32x2 %0, %1, %2;" : "=l"(d) : "l"(a), "l"(b)); return d;
}
__device__ __forceinline__ void unpack2(ull v, float& lo, float& hi) {
    asm("mov.b64 {%0,%1}, %2;" : "=f"(lo), "=f"(hi) : "l"(v));
}

// Accurate tanh via ex2/rcp (~1e-7) — RNN cell only (feeds h_final undamped).
__device__ __forceinline__ float fast_tanh(float x) {
    float e;
    asm("ex2.approx.f32 %0, %1;" : "=f"(e) : "f"(x * 2.8853900817779268f));
    float r;
    asm("rcp.approx.f32 %0, %1;" : "=f"(r) : "f"(e + 1.0f));
    return fmaf(-2.0f, r, 1.0f);
}

// HW tanh (MUFU.TANH) — vector field only (errors damped by the RNN cell).
__device__ __forceinline__ float hw_tanh(float x) {
    float y;
    asm("tanh.approx.f32 %0, %1;" : "=f"(y) : "f"(x));
    return y;
}

// ============ pre-kernel: g_U[bn][perm(j)] = Wx[j]@obs[bn] + bx[j] ============
#define GR 16
__global__ void __launch_bounds__(256) wx_kernel(
    const float* __restrict__ obs, const float* __restrict__ Wx,
    const float* __restrict__ bx)
{
    __shared__ float sWT[32 * 64];
    __shared__ float sB[64];
    __shared__ float sO[GR * 32];
    const int tid = threadIdx.x;
    for (int e = tid; e < 2048; e += 256) sWT[e] = Wx[(e & 63) * 32 + (e >> 6)];
    if (tid < 64) sB[tid] = bx[tid];
    const size_t base = (size_t)blockIdx.x * GR;
    for (int e = tid; e < GR * 32; e += 256) sO[e] = obs[base * 32 + e];
    __syncthreads();
    const int j = tid & 63, m0 = tid >> 6;
    const int jp = (j < 32) ? (2 * j) : (2 * (j - 32) + 1);   // interleave
#pragma unroll
    for (int m = m0; m < GR; m += 4) {
        const float* x = sO + m * 32;
        float acc = sB[j];
#pragma unroll
        for (int i = 0; i < 32; i++) acc = fmaf(sWT[i * 64 + j], x[i], acc);
        g_U[(base + m) * 64 + jp] = acc;
    }
}

// ============ sequential ODE-RNN: 2 warps/block, 1 seq/warp ============
__global__ void __launch_bounds__(64, 1) ode_rnn_kernel(
    const float* __restrict__ ts,
    const float* __restrict__ scale_p,
    const float* __restrict__ w0, const float* __restrict__ b0,
    const float* __restrict__ w1, const float* __restrict__ b1,
    const float* __restrict__ w2, const float* __restrict__ b2,
    const float* __restrict__ Wh,
    const float* __restrict__ ow0, const float* __restrict__ ob0,
    const float* __restrict__ ow1, const float* __restrict__ ob1,
    const float* __restrict__ ow2, const float* __restrict__ ob2,
    float* __restrict__ out)
{
    // Wh interleaved by row-pair: sWhI[p*PITCH + 2c + s] = Wh[(s*32+p)*64 + c]
    __shared__ __align__(16) float sWhI[32 * WHI_PITCH];
    __shared__ __align__(16) float sX[2][64];     // h (vf input), per warp
    __shared__ __align__(16) float2 sH2[2][64];   // duplicated y pairs per warp

    const int tid = threadIdx.x;
    const int w   = tid >> 5;
    const int l   = tid & 31;
    const int seq = blockIdx.x * 2 + w;

    for (int e = tid; e < 64 * 64; e += 64) {
        int row = e >> 6, col = e & 63;
        sWhI[(row & 31) * WHI_PITCH + col * 2 + (row >> 5)] = Wh[e];
    }
    __syncthreads();

    const int r    = l & 15;
    const int half = l >> 4;
    const float scale = scale_p[0];

    // ---- register-resident ODE-MLP weights ----
    ull w0p[16];
#pragma unroll
    for (int j = 0; j < 16; j++)
        w0p[j] = pack2(w0[r * 65 + 1 + half * 32 + 2 * j],
                       w0[r * 65 + 1 + half * 32 + 2 * j + 1]);
    const float w0t = half ? 0.0f : w0[r * 65];
    const float b0r = half ? 0.0f : b0[r];
    // layer2: FULL row r per lane (lanes r and r+16 duplicate)
    float w1v[16];
#pragma unroll
    for (int j = 0; j < 16; j++) w1v[j] = w1[r * 16 + j];
    const float b1r = b1[r];
    ull w2p[16];   // (row l, row l+32) weight pairs per column j
#pragma unroll
    for (int j = 0; j < 16; j++)
        w2p[j] = pack2(w2[l * 16 + j], w2[(l + 32) * 16 + j]);
    const ull b2p = pack2(b2[l], b2[l + 32]);

    float* const sX0 = sX[w];
    float2* const sHw = sH2[w];
    const ulonglong2* const whp = reinterpret_cast<const ulonglong2*>(sWhI + l * WHI_PITCH);
    const ulonglong2* const hp  = reinterpret_cast<const ulonglong2*>(sHw);
    const ulonglong2* const xs  = reinterpret_cast<const ulonglong2*>(sX0 + half * 32);

    // vector field at (t, h) with h already in sX0:
    // g = tanh(tanh(w2 @ tanh(w1 @ tanh(w0 @ [t,h]))))   (scale folded into dts)
    auto vf = [&](float t, float& f0, float& f1) {
        // layer 1: packed f32x2 pairs straight from smem
        ull aA = 0ull, aB = 0ull, aC = 0ull, aD = 0ull;
        {
            ulonglong2 x0 = xs[0], x1 = xs[1], x2 = xs[2], x3 = xs[3];
            ulonglong2 x4 = xs[4], x5 = xs[5], x6 = xs[6], x7 = xs[7];
            aA = fma2(w0p[0],  x0.x, aA); aB = fma2(w0p[1],  x0.y, aB);
            aC = fma2(w0p[2],  x1.x, aC); aD = fma2(w0p[3],  x1.y, aD);
            aA = fma2(w0p[4],  x2.x, aA); aB = fma2(w0p[5],  x2.y, aB);
            aC = fma2(w0p[6],  x3.x, aC); aD = fma2(w0p[7],  x3.y, aD);
            aA = fma2(w0p[8],  x4.x, aA); aB = fma2(w0p[9],  x4.y, aB);
            aC = fma2(w0p[10], x5.x, aC); aD = fma2(w0p[11], x5.y, aD);
            aA = fma2(w0p[12], x6.x, aA); aB = fma2(w0p[13], x6.y, aB);
            aC = fma2(w0p[14], x7.x, aC); aD = fma2(w0p[15], x7.y, aD);
        }
        float s_lo, s_hi;
        unpack2(add2(add2(aA, aB), add2(aC, aD)), s_lo, s_hi);
        float acc = (s_lo + s_hi) + fmaf(w0t, t, b0r);
        acc += __shfl_xor_sync(FULLMASK, acc, 16);
        float z0 = hw_tanh(acc);                 // z0[r] on lanes r and r+16
        // layer 2: full row per lane; no cross-lane reduction afterwards
        float p0 = b1r, p1 = 0.f, p2 = 0.f, p3 = 0.f;
#pragma unroll
        for (int j = 0; j < 16; j += 4) {
            float za = __shfl_sync(FULLMASK, z0, j);
            float zb = __shfl_sync(FULLMASK, z0, j + 1);
            float zc = __shfl_sync(FULLMASK, z0, j + 2);
            float zd = __shfl_sync(FULLMASK, z0, j + 3);
            p0 = fmaf(w1v[j],     za, p0);
            p1 = fmaf(w1v[j + 1], zb, p1);
            p2 = fmaf(w1v[j + 2], zc, p2);
            p3 = fmaf(w1v[j + 3], zd, p3);
        }
        float z1 = hw_tanh((p0 + p1) + (p2 + p3));  // z1[r] on lanes r, r+16
        // layer 3: packed (row l, row l+32) accumulators
        ull u0 = b2p, u1 = 0ull, u2 = 0ull, u3 = 0ull;
#pragma unroll
        for (int j = 0; j < 16; j += 4) {
            float za = __shfl_sync(FULLMASK, z1, j);
            float zb = __shfl_sync(FULLMASK, z1, j + 1);
            float zc = __shfl_sync(FULLMASK, z1, j + 2);
            float zd = __shfl_sync(FULLMASK, z1, j + 3);
            u0 = fma2(w2p[j],     pack2(za, za), u0);
            u1 = fma2(w2p[j + 1], pack2(zb, zb), u1);
            u2 = fma2(w2p[j + 2], pack2(zc, zc), u2);
            u3 = fma2(w2p[j + 3], pack2(zd, zd), u3);
        }
        float v0, v1;
        unpack2(add2(add2(u0, u1), add2(u2, u3)), v0, v1);
        f0 = hw_tanh(hw_tanh(v0));
        f1 = hw_tanh(hw_tanh(v1));
    };

    float h0 = 0.f, h1 = 0.f;
    float t_prev = __ldg(ts + seq * SEQLEN);
    const float* Useq = g_U + (size_t)seq * SEQLEN * HDIM;
    const float2* U2  = reinterpret_cast<const float2*>(Useq);  // 32 float2 per obs

    // initial vf-input store (h = 0) + first prefetch
    sX0[l] = 0.f;
    sX0[l + 32] = 0.f;
    float  t_next = t_prev;                        // t[0]
    float2 u_next = __ldg(U2 + l);                 // U[0], interleaved pair
    __syncwarp();

#pragma unroll 1
    for (int n = 0; n < SEQLEN; n++) {
        float  t_n = t_next;
        float2 u   = u_next;
        // prefetch next iteration's t/U with a full iteration of slack
        int np = (n + 1 < SEQLEN) ? (n + 1) : n;
        t_next = __ldg(ts + seq * SEQLEN + np);
        u_next = __ldg(U2 + np * 32 + l);
        float dts = (t_n - t_prev) * scale;

        // ---- forward Euler: y = h + dts * f(t_prev, h) ----
        float k0, k1;
        vf(t_prev, k0, k1);
        float y0 = fmaf(dts, k0, h0);
        float y1 = fmaf(dts, k1, h1);

        // ---- RNN cell: h = tanh(Wh @ y + U_n), 8 packed accumulators ----
        sHw[l]      = make_float2(y0, y0);
        sHw[l + 32] = make_float2(y1, y1);
        __syncwarp();
        ull rA = 0ull, rB = 0ull, rC = 0ull, rD = 0ull;
        ull rE = 0ull, rF = 0ull, rG = 0ull, rH = 0ull;
#pragma unroll
        for (int i = 0; i < 32; i += 4) {
            ulonglong2 wv0 = whp[i],     hv0 = hp[i];
            ulonglong2 wv1 = whp[i + 1], hv1 = hp[i + 1];
            ulonglong2 wv2 = whp[i + 2], hv2 = hp[i + 2];
            ulonglong2 wv3 = whp[i + 3], hv3 = hp[i + 3];
            rA = fma2(wv0.x, hv0.x, rA);
            rB = fma2(wv0.y, hv0.y, rB);
            rC = fma2(wv1.x, hv1.x, rC);
            rD = fma2(wv1.y, hv1.y, rD);
            rE = fma2(wv2.x, hv2.x, rE);
            rF = fma2(wv2.y, hv2.y, rF);
            rG = fma2(wv3.x, hv3.x, rG);
            rH = fma2(wv3.y, hv3.y, rH);
        }
        float v0, v1;
        unpack2(add2(add2(add2(rA, rB), add2(rC, rD)),
                     add2(add2(rE, rF), add2(rG, rH))), v0, v1);
        h0 = fast_tanh(v0 + u.x);                 // U folded in at the tail
        h1 = fast_tanh(v1 + u.y);
        t_prev = t_n;

        // publish h for the next vf (one sync serves both orderings)
        sX0[l]      = h0;
        sX0[l + 32] = h1;
        __syncwarp();
    }

    // ---- write h_final ----
    out[BATCH * 8 + seq * 64 + l]      = h0;
    out[BATCH * 8 + seq * 64 + 32 + l] = h1;

    // ---- output MLP: relu(ow0@h+ob0) -> relu(ow1@.+ob1) -> ow2@.+ob2 ----
    // (sX0 already holds h)
    float a0 = 0.f, a1 = 0.f;
#pragma unroll
    for (int j = 0; j < 32; j += 2) {
        a0 = fmaf(__ldg(ow0 + r * 64 + half * 32 + j),     sX0[half * 32 + j],     a0);
        a1 = fmaf(__ldg(ow0 + r * 64 + half * 32 + j + 1), sX0[half * 32 + j + 1], a1);
    }
    float acc = a0 + a1 + (half ? 0.f : __ldg(ob0 + r));
    acc += __shfl_xor_sync(FULLMASK, acc, 16);
    float z0 = fmaxf(acc, 0.f);

    float p = half ? 0.f : __ldg(ob1 + r);
#pragma unroll
    for (int j = 0; j < 8; j++) {
        float zz = __shfl_sync(FULLMASK, z0, half * 8 + j);
        p = fmaf(__ldg(ow1 + r * 16 + half * 8 + j), zz, p);
    }
    p += __shfl_xor_sync(FULLMASK, p, 16);
    float z1 = fmaxf(p, 0.f);

    int orow = l < 8 ? l : 7;
    float o = __ldg(ob2 + orow);
#pragma unroll
    for (int j = 0; j < 16; j++) {
        float zz = __shfl_sync(FULLMASK, z1, j);
        o = fmaf(__ldg(ow2 + orow * 16 + j), zz, o);
    }
    if (l < 8) out[seq * 8 + l] = o;
}

extern "C" void kernel_launch(void* const* d_in, const int* in_sizes, int n_in,
                              void* d_out, int out_size) {
    (void)in_sizes; (void)n_in; (void)out_size;
    // inputs: 0 ts, 1 obs, 2 scale, 3 w0, 4 b0, 5 w1, 6 b1, 7 w2, 8 b2,
    //         9 Wh, 10 Wx, 11 bx, 12 ow0, 13 ob0, 14 ow1, 15 ob1, 16 ow2, 17 ob2
    wx_kernel<<<(BATCH * SEQLEN) / GR, 256>>>(
        (const float*)d_in[1], (const float*)d_in[10], (const float*)d_in[11]);
    ode_rnn_kernel<<<BATCH / 2, 64>>>(
        (const float*)d_in[0],  (const float*)d_in[2],
        (const float*)d_in[3],  (const float*)d_in[4],
        (const float*)d_in[5],  (const float*)d_in[6],
        (const float*)d_in[7],  (const float*)d_in[8],
        (const float*)d_in[9],
        (const float*)d_in[12], (const float*)d_in[13],
        (const float*)d_in[14], (const float*)d_in[15],
        (const float*)d_in[16], (const float*)d_in[17],
        (float*)d_out);
}